// round 15
// baseline (speedup 1.0000x reference)
#include <cuda_runtime.h>

#define Bn   256
#define Tn   512
#define Dn   64
#define En   128
#define H1n  128
#define H2n  64
#define Vn   10000
#define ML   30
#define SOS_ 1
#define EOS_ 2

typedef unsigned long long ull;

// ---------------- persistent state + prepped weights (device globals) -------
__device__ float g_h1[2][Bn * H1n];        // ping-pong
__device__ float g_c1[Bn * H1n];
__device__ float g_h2[2][Bn * H2n];        // ping-pong
__device__ float g_c2[Bn * H2n];
__device__ float g_x[Bn * 128];            // [h2(64) | ctx(64)] pred input
__device__ ull   g_amax[Bn];               // packed (fkey(val)<<32 | ~v)

// per-block contiguous, gate-interleaved weight slices
__device__ float g_w1B[8][320][64];        // [rowtile][k][row-in-tile]
__device__ float g_w2B[4][192][64];
__device__ float g_wpB[79][128][128];      // [vtile][k][v-in-tile], zero-padded
__device__ float g_b1R[512];
__device__ float g_b2R[256];
__device__ float g_wqT[64 * 64];           // [k][d]

__device__ __forceinline__ unsigned int fkey(float f) {
    unsigned int u = __float_as_uint(f);
    return (u & 0x80000000u) ? ~u : (u | 0x80000000u);
}
__device__ __forceinline__ float sigm(float x) { return 1.0f / (1.0f + expf(-x)); }

__device__ __forceinline__ void fma2(ull& d, ull a, ull b) {
    asm("fma.rn.f32x2 %0, %1, %2, %0;" : "+l"(d) : "l"(a), "l"(b));
}
__device__ __forceinline__ void add2(ull& d, ull a) {
    asm("add.rn.f32x2 %0, %0, %1;" : "+l"(d) : "l"(a));
}
__device__ __forceinline__ ull dup2(float x) {
    unsigned int u = __float_as_uint(x); ull r;
    asm("mov.b64 %0, {%1, %1};" : "=l"(r) : "r"(u));
    return r;
}
__device__ __forceinline__ void unpk2(ull a, float& lo, float& hi) {
    unsigned int ul, uh;
    asm("mov.b64 {%0, %1}, %2;" : "=r"(ul), "=r"(uh) : "l"(a));
    lo = __uint_as_float(ul); hi = __uint_as_float(uh);
}
__device__ __forceinline__ void cpa16(void* s, const void* g) {
    unsigned sa = (unsigned)__cvta_generic_to_shared(s);
    asm volatile("cp.async.cg.shared.global [%0], [%1], 16;" :: "r"(sa), "l"(g));
}
#define CP_COMMIT()  asm volatile("cp.async.commit_group;")
#define CP_WAIT0()   asm volatile("cp.async.wait_group 0;")

// ---------------- one-time prep ---------------------------------------------
__global__ void k_prep_small(const float* __restrict__ wih1, const float* __restrict__ whh1,
                             const float* __restrict__ bih1, const float* __restrict__ bhh1,
                             const float* __restrict__ wih2, const float* __restrict__ whh2,
                             const float* __restrict__ bih2, const float* __restrict__ bhh2,
                             const float* __restrict__ wq) {
    int n = blockDim.x * gridDim.x;
    int t0 = blockIdx.x * blockDim.x + threadIdx.x;
    for (int i = t0; i < 8 * 320 * 64; i += n) {
        int rt = i / (320 * 64), rem = i - rt * 320 * 64;
        int k = rem >> 6, j = rem & 63;
        int c = rt * 64 + j;
        int h = c >> 2, g = c & 3, r = g * 128 + h;
        ((float*)g_w1B)[i] = (k < 192) ? wih1[r * 192 + k] : whh1[r * 128 + (k - 192)];
    }
    for (int i = t0; i < 4 * 192 * 64; i += n) {
        int rt = i / (192 * 64), rem = i - rt * 192 * 64;
        int k = rem >> 6, j = rem & 63;
        int c = rt * 64 + j;
        int h = c >> 2, g = c & 3, r = g * 64 + h;
        ((float*)g_w2B)[i] = (k < 128) ? wih2[r * 128 + k] : whh2[r * 64 + (k - 128)];
    }
    for (int i = t0; i < 64 * 64; i += n) {
        int k = i >> 6, d = i & 63;
        g_wqT[i] = wq[d * 64 + k];
    }
    for (int c = t0; c < 512; c += n) {
        int h = c >> 2, g = c & 3, r = g * 128 + h;
        g_b1R[c] = bih1[r] + bhh1[r];
    }
    for (int c = t0; c < 256; c += n) {
        int h = c >> 2, g = c & 3, r = g * 64 + h;
        g_b2R[c] = bih2[r] + bhh2[r];
    }
}

// tiled transpose wp[10000][128] -> g_wpB[79][128][128] (zero-padded)
__global__ void k_prep_wp(const float* __restrict__ wp) {
    __shared__ float t[32][33];
    int v0 = blockIdx.x * 32, kt = blockIdx.y * 32;
    int tx = threadIdx.x & 31, ty = threadIdx.x >> 5;   // 32 x 8
    #pragma unroll
    for (int i = 0; i < 4; i++) {
        int v = v0 + ty + i * 8;
        t[ty + i * 8][tx] = (v < Vn) ? wp[(size_t)v * 128 + kt + tx] : 0.f;
    }
    __syncthreads();
    int v = v0 + tx;
    #pragma unroll
    for (int i = 0; i < 4; i++) {
        int k = kt + ty + i * 8;
        g_wpB[v >> 7][k][v & 127] = t[tx][ty + i * 8];
    }
}

__global__ void k_init() {
    int i = blockIdx.x * blockDim.x + threadIdx.x;
    if (i < Bn * H1n) { g_h1[0][i] = 0.f; g_h1[1][i] = 0.f; g_c1[i] = 0.f; }
    if (i < Bn * H2n) { g_h2[0][i] = 0.f; g_h2[1][i] = 0.f; g_c2[i] = 0.f; }
    if (i < Bn * 128) g_x[i] = 0.f;
    if (i < Bn) g_amax[i] = (ull)(~(unsigned int)SOS_);
}

// ---------------- k_lstm1: grid (8 rowtiles, 16 btiles), 512 thr (R13) ------
#define L1_TOK   0
#define L1_SW    128                                // [320][64] f  = 81920
#define L1_SXD   (128 + 81920)                      // [320][18] ull = 46080
#define L1_SR    (L1_SXD + 46080)                   // [3][128][4] ull = 12288
#define L1_SG    (L1_SR + 12288)                    // [64][18] f   = 4608
#define L1_SMEM  (L1_SG + 4608)

__global__ void __launch_bounds__(512) k_lstm1(const float* __restrict__ emb, int p) {
    extern __shared__ __align__(16) char sm[];
    int*  s_tok       = (int*)(sm + L1_TOK);
    float (*s_w)[64]  = (float(*)[64])(sm + L1_SW);
    ull   (*s_xd)[18] = (ull(*)[18])(sm + L1_SXD);
    ull   (*s_r)[128][4] = (ull(*)[128][4])(sm + L1_SR);
    float (*s_g)[18]  = (float(*)[18])(sm + L1_SG);

    const int tid = threadIdx.x;
    const int rt = blockIdx.x, bt = blockIdx.y;
    const int r0 = rt * 64, b0 = bt * 16;
    const float* __restrict__ h1old = g_h1[p];
    float* __restrict__ h1new = g_h1[p ^ 1];

    {
        const float* src = &g_w1B[rt][0][0];
        #pragma unroll
        for (int i = 0; i < 10; i++) {
            int idx = tid + i * 512;
            cpa16((char*)&s_w[0][0] + idx * 16, src + idx * 4);
        }
    }
    CP_COMMIT();

    if (tid < 16) {
        ull a = g_amax[b0 + tid];
        s_tok[tid] = (int)(~(unsigned int)(a & 0xFFFFFFFFull));
    }
    __syncthreads();

    for (int i = 0; i < 10; i++) {
        int idx = tid + i * 512;
        int b = idx / 320, k = idx - b * 320;
        float v;
        if (k < 128) {
            int t = s_tok[b];
            v = (t == EOS_) ? 0.f : emb[(size_t)t * En + k];
        } else if (k < 192) {
            v = g_x[(b0 + b) * 128 + 64 + (k - 128)];
        } else {
            v = h1old[(b0 + b) * H1n + (k - 192)];
        }
        s_xd[k][b] = dup2(v);
    }
    CP_WAIT0();
    __syncthreads();

    const int kg = tid >> 7;
    const int t7 = tid & 127;
    const int RQ = t7 >> 3, Bg = t7 & 7;
    ull a00 = 0, a01 = 0, a10 = 0, a11 = 0;

    {
        const int k0 = kg * 80;
        #pragma unroll 8
        for (int kk = k0; kk < k0 + 80; kk++) {
            ulonglong2 w2 = *(const ulonglong2*)&s_w[kk][4 * RQ];
            ulonglong2 x2 = *(const ulonglong2*)&s_xd[kk][2 * Bg];
            fma2(a00, w2.x, x2.x); fma2(a01, w2.x, x2.y);
            fma2(a10, w2.y, x2.x); fma2(a11, w2.y, x2.y);
        }
    }

    if (kg > 0) {
        s_r[kg - 1][t7][0] = a00; s_r[kg - 1][t7][1] = a01;
        s_r[kg - 1][t7][2] = a10; s_r[kg - 1][t7][3] = a11;
    }
    __syncthreads();
    if (kg == 0) {
        #pragma unroll
        for (int j = 0; j < 3; j++) {
            add2(a00, s_r[j][t7][0]); add2(a01, s_r[j][t7][1]);
            add2(a10, s_r[j][t7][2]); add2(a11, s_r[j][t7][3]);
        }
        float b0v = g_b1R[r0 + 4 * RQ],     b1v = g_b1R[r0 + 4 * RQ + 1];
        float b2v = g_b1R[r0 + 4 * RQ + 2], b3v = g_b1R[r0 + 4 * RQ + 3];
        float v0, v1;
        unpk2(a00, v0, v1);
        s_g[4 * RQ][2 * Bg] = v0 + b0v; s_g[4 * RQ + 1][2 * Bg] = v1 + b1v;
        unpk2(a01, v0, v1);
        s_g[4 * RQ][2 * Bg + 1] = v0 + b0v; s_g[4 * RQ + 1][2 * Bg + 1] = v1 + b1v;
        unpk2(a10, v0, v1);
        s_g[4 * RQ + 2][2 * Bg] = v0 + b2v; s_g[4 * RQ + 3][2 * Bg] = v1 + b3v;
        unpk2(a11, v0, v1);
        s_g[4 * RQ + 2][2 * Bg + 1] = v0 + b2v; s_g[4 * RQ + 3][2 * Bg + 1] = v1 + b3v;
    }
    __syncthreads();

    if (tid < 256) {
        int b = tid & 15, hl = tid >> 4;
        float gi = s_g[4 * hl][b],     gf = s_g[4 * hl + 1][b];
        float gg = s_g[4 * hl + 2][b], go = s_g[4 * hl + 3][b];
        int gidx = (b0 + b) * H1n + rt * 16 + hl;
        float c = sigm(gf) * g_c1[gidx] + sigm(gi) * tanhf(gg);
        g_c1[gidx] = c;
        h1new[gidx] = sigm(go) * tanhf(c);
    }
}

// ---------------- k_lstm2: grid (4 rowtiles, 16 btiles), 512 thr (R13) ------
#define L2_SW    0                                  // [192][64] f  = 49152
#define L2_SXD   49152                              // [192][18] ull = 27648
#define L2_SR    (49152 + 27648)                    // [3][128][4] ull = 12288
#define L2_SG    (L2_SR + 12288)                    // 4608
#define L2_SMEM  (L2_SG + 4608)

__global__ void __launch_bounds__(512) k_lstm2(int p) {
    extern __shared__ __align__(16) char sm[];
    float (*s_w)[64]  = (float(*)[64])(sm + L2_SW);
    ull   (*s_xd)[18] = (ull(*)[18])(sm + L2_SXD);
    ull   (*s_r)[128][4] = (ull(*)[128][4])(sm + L2_SR);
    float (*s_g)[18]  = (float(*)[18])(sm + L2_SG);

    const int tid = threadIdx.x;
    const int rt = blockIdx.x, bt = blockIdx.y;
    const int r0 = rt * 64, b0 = bt * 16;
    const float* __restrict__ h1new = g_h1[p ^ 1];
    const float* __restrict__ h2old = g_h2[p];
    float* __restrict__ h2new = g_h2[p ^ 1];

    {
        const float* src = &g_w2B[rt][0][0];
        #pragma unroll
        for (int i = 0; i < 6; i++) {
            int idx = tid + i * 512;
            cpa16((char*)&s_w[0][0] + idx * 16, src + idx * 4);
        }
    }
    CP_COMMIT();

    for (int i = 0; i < 6; i++) {
        int idx = tid + i * 512;
        int b = idx / 192, k = idx - b * 192;
        float v = (k < 128) ? h1new[(b0 + b) * H1n + k]
                            : h2old[(b0 + b) * H2n + (k - 128)];
        s_xd[k][b] = dup2(v);
    }
    CP_WAIT0();
    __syncthreads();

    const int kg = tid >> 7;
    const int t7 = tid & 127;
    const int RQ = t7 >> 3, Bg = t7 & 7;
    ull a00 = 0, a01 = 0, a10 = 0, a11 = 0;

    {
        const int k0 = kg * 48;
        #pragma unroll 8
        for (int kk = k0; kk < k0 + 48; kk++) {
            ulonglong2 w2 = *(const ulonglong2*)&s_w[kk][4 * RQ];
            ulonglong2 x2 = *(const ulonglong2*)&s_xd[kk][2 * Bg];
            fma2(a00, w2.x, x2.x); fma2(a01, w2.x, x2.y);
            fma2(a10, w2.y, x2.x); fma2(a11, w2.y, x2.y);
        }
    }

    if (kg > 0) {
        s_r[kg - 1][t7][0] = a00; s_r[kg - 1][t7][1] = a01;
        s_r[kg - 1][t7][2] = a10; s_r[kg - 1][t7][3] = a11;
    }
    __syncthreads();
    if (kg == 0) {
        #pragma unroll
        for (int j = 0; j < 3; j++) {
            add2(a00, s_r[j][t7][0]); add2(a01, s_r[j][t7][1]);
            add2(a10, s_r[j][t7][2]); add2(a11, s_r[j][t7][3]);
        }
        float b0v = g_b2R[r0 + 4 * RQ],     b1v = g_b2R[r0 + 4 * RQ + 1];
        float b2v = g_b2R[r0 + 4 * RQ + 2], b3v = g_b2R[r0 + 4 * RQ + 3];
        float v0, v1;
        unpk2(a00, v0, v1);
        s_g[4 * RQ][2 * Bg] = v0 + b0v; s_g[4 * RQ + 1][2 * Bg] = v1 + b1v;
        unpk2(a01, v0, v1);
        s_g[4 * RQ][2 * Bg + 1] = v0 + b0v; s_g[4 * RQ + 1][2 * Bg + 1] = v1 + b1v;
        unpk2(a10, v0, v1);
        s_g[4 * RQ + 2][2 * Bg] = v0 + b2v; s_g[4 * RQ + 3][2 * Bg] = v1 + b3v;
        unpk2(a11, v0, v1);
        s_g[4 * RQ + 2][2 * Bg + 1] = v0 + b2v; s_g[4 * RQ + 3][2 * Bg + 1] = v1 + b3v;
    }
    __syncthreads();

    if (tid < 256) {
        int b = tid & 15, hl = tid >> 4;
        float gi = s_g[4 * hl][b],     gf = s_g[4 * hl + 1][b];
        float gg = s_g[4 * hl + 2][b], go = s_g[4 * hl + 3][b];
        int gidx = (b0 + b) * H2n + rt * 16 + hl;
        float c = sigm(gf) * g_c2[gidx] + sigm(gi) * tanhf(gg);
        g_c2[gidx] = c;
        float h = sigm(go) * tanhf(c);
        h2new[gidx] = h;
        g_x[(b0 + b) * 128 + rt * 16 + hl] = h;
    }
}

// ---------------- attention (unchanged) -------------------------------------
__global__ void __launch_bounds__(256) k_attn(
    const float* __restrict__ enc_key, const float* __restrict__ enc_val,
    const int* __restrict__ mask, const float* __restrict__ bq)
{
    __shared__ __align__(16) float s_q[64];
    __shared__ float s_h2[64];
    __shared__ float s_qp[4][64];
    __shared__ float s_e[512];
    __shared__ float s_w[512];
    __shared__ float s_red[40];
    __shared__ float s_p[4][64];
    const int b = blockIdx.x, tid = threadIdx.x;
    const int lane = tid & 31, warp = tid >> 5;

    if (tid == 0) g_amax[b] = 0ull;
    if (tid < 64) s_h2[tid] = g_x[b * 128 + tid];
    __syncthreads();

    {
        int d = tid & 63, kq = tid >> 6;
        float a = 0.f;
        #pragma unroll
        for (int k = kq * 16; k < kq * 16 + 16; k++)
            a += g_wqT[k * 64 + d] * s_h2[k];
        s_qp[kq][d] = a;
    }
    __syncthreads();
    if (tid < 64)
        s_q[tid] = s_qp[0][tid] + s_qp[1][tid] + s_qp[2][tid] + s_qp[3][tid] + bq[tid];
    __syncthreads();

    {
        const int slot = tid >> 2, dq = tid & 3;
        const float4* qp = (const float4*)(s_q + dq * 16);
        float4 q0 = qp[0], q1 = qp[1], q2 = qp[2], q3 = qp[3];
        #pragma unroll 4
        for (int i = 0; i < 8; i++) {
            int t = slot + 64 * i;
            const float4* kp = (const float4*)(enc_key + ((size_t)t * Bn + b) * Dn + dq * 16);
            float4 a = kp[0], c = kp[1], d = kp[2], e = kp[3];
            float pp = a.x * q0.x + a.y * q0.y + a.z * q0.z + a.w * q0.w
                     + c.x * q1.x + c.y * q1.y + c.z * q1.z + c.w * q1.w
                     + d.x * q2.x + d.y * q2.y + d.z * q2.z + d.w * q2.w
                     + e.x * q3.x + e.y * q3.y + e.z * q3.z + e.w * q3.w;
            pp += __shfl_xor_sync(0xffffffffu, pp, 1);
            pp += __shfl_xor_sync(0xffffffffu, pp, 2);
            if (dq == 0) s_e[t] = pp;
        }
    }
    __syncthreads();

    float e0 = s_e[tid], e1 = s_e[tid + 256];
    float mx = fmaxf(e0, e1);
    #pragma unroll
    for (int o = 16; o; o >>= 1) mx = fmaxf(mx, __shfl_xor_sync(0xffffffffu, mx, o));
    if (lane == 0) s_red[warp] = mx;
    __syncthreads();
    if (tid == 0) {
        float m = s_red[0];
        #pragma unroll
        for (int i = 1; i < 8; i++) m = fmaxf(m, s_red[i]);
        s_red[32] = m;
    }
    __syncthreads();
    mx = s_red[32];
    int m0 = mask[(size_t)b * Tn + tid], m1 = mask[(size_t)b * Tn + tid + 256];
    float x0 = expf(e0 - mx), x1 = expf(e1 - mx);
    float s = x0 + x1, ws = (m0 ? x0 : 0.f) + (m1 ? x1 : 0.f);
    #pragma unroll
    for (int o = 16; o; o >>= 1) {
        s  += __shfl_xor_sync(0xffffffffu, s,  o);
        ws += __shfl_xor_sync(0xffffffffu, ws, o);
    }
    if (lane == 0) { s_red[warp] = s; s_red[8 + warp] = ws; }
    __syncthreads();
    if (tid == 0) {
        float S = 0.f, W = 0.f;
        #pragma unroll
        for (int i = 0; i < 8; i++) { S += s_red[i]; W += s_red[8 + i]; }
        s_red[33] = 1.0f / (S * fmaxf(W / S, 2e-30f));
    }
    __syncthreads();
    float inv = s_red[33];
    s_w[tid]       = m0 ? x0 * inv : 0.f;
    s_w[tid + 256] = m1 ? x1 * inv : 0.f;
    __syncthreads();

    {
        int d = tid & 63, ch = tid >> 6;
        const float* vb = enc_val + (size_t)b * Dn + d;
        float a0 = 0.f, a1 = 0.f;
        #pragma unroll 4
        for (int t = ch * 128; t < ch * 128 + 128; t += 2) {
            a0 += s_w[t]     * vb[(size_t)t * (Bn * Dn)];
            a1 += s_w[t + 1] * vb[(size_t)(t + 1) * (Bn * Dn)];
        }
        s_p[ch][d] = a0 + a1;
    }
    __syncthreads();
    if (tid < 64) {
        float c = s_p[0][tid] + s_p[1][tid] + s_p[2][tid] + s_p[3][tid];
        g_x[b * 128 + 64 + tid] = c;
    }
}

// ---------------- pred GEMM: b-split (no combine), fused argmax -------------
// grid (79, 8), 512 thr = 2 b-halves x (32 vq x 8 bg of 2 b), full k=128.
#define KP_SWT   0                                  // [128][128] f  = 65536
#define KP_SXD   65536                              // [32][128] ull = 32768
#define KP_SMEM  (65536 + 32768)

__global__ void __launch_bounds__(512) k_pred(const float* __restrict__ bp,
                                              float* __restrict__ out, int step) {
    extern __shared__ __align__(16) char sm[];
    float (*s_wt)[128] = (float(*)[128])(sm + KP_SWT);
    ull   (*s_xd)[128] = (ull(*)[128])(sm + KP_SXD);
    const int tid = threadIdx.x;
    const int b0 = blockIdx.y * 32;
    const int vt = blockIdx.x;

    // stage all 128 weight rows (contiguous zero-padded slice, no guards)
    {
        const float* src = &g_wpB[vt][0][0];
        #pragma unroll
        for (int i = 0; i < 8; i++) {
            int idx = tid + i * 512;                // 4096 float4 slots
            cpa16((char*)&s_wt[0][0] + idx * 16, src + idx * 4);
        }
    }
    CP_COMMIT();

    // x fill: 32 b x 128 k dup pairs (coalesced LDG, b-major)
    for (int i = 0; i < 8; i++) {
        int idx = tid + i * 512;                // 4096 elements
        int b = idx >> 7, k = idx & 127;
        s_xd[b][k] = dup2(g_x[(b0 + b) * 128 + k]);
    }
    CP_WAIT0();
    __syncthreads();

    const int bh = tid >> 8;                 // b half: 16 b each
    const int t8 = tid & 255;
    const int vq = t8 & 31, bg = t8 >> 5;    // 32 v-quads x 8 b-pairs
    const int bb0 = bh * 16 + bg * 2;        // this thread's 2 b rows
    const int v0 = vt * 128 + vq * 4;
    const bool vok = (v0 + 3) < Vn;

    ull acc[2][2] = {};                      // [vpair][b]
    #pragma unroll 4
    for (int kk = 0; kk < 128; kk++) {
        ulonglong2 w = *(const ulonglong2*)&s_wt[kk][vq * 4];
        ull xd0 = s_xd[bb0][kk];
        ull xd1 = s_xd[bb0 + 1][kk];
        fma2(acc[0][0], w.x, xd0); fma2(acc[0][1], w.x, xd1);
        fma2(acc[1][0], w.y, xd0); fma2(acc[1][1], w.y, xd1);
    }

    float bs0 = 0.f, bs1 = 0.f, bs2 = 0.f, bs3 = 0.f;
    if (vok) {
        float4 b4 = *(const float4*)&bp[v0];
        bs0 = b4.x; bs1 = b4.y; bs2 = b4.z; bs3 = b4.w;
    }

    #pragma unroll
    for (int b = 0; b < 2; b++) {
        int bi = b0 + bb0 + b;
        float r0, r1, r2, r3;
        unpk2(acc[0][b], r0, r1);
        unpk2(acc[1][b], r2, r3);
        r0 += bs0; r1 += bs1; r2 += bs2; r3 += bs3;
        if (vok) {
            __stcs((float4*)(out + (size_t)bi * (ML * Vn) + (size_t)step * Vn + v0),
                   make_float4(r0, r1, r2, r3));
        }
        float best = r0; int bv = v0;
        if (r1 > best) { best = r1; bv = v0 + 1; }
        if (r2 > best) { best = r2; bv = v0 + 2; }
        if (r3 > best) { best = r3; bv = v0 + 3; }
        ull pk = vok ? (((ull)fkey(best) << 32) | (unsigned int)(~bv)) : 0ull;
        #pragma unroll
        for (int o = 16; o; o >>= 1) {
            ull other = __shfl_down_sync(0xffffffffu, pk, o);
            if (other > pk) pk = other;
        }
        if (vq == 0) atomicMax(&g_amax[bi], pk);
    }
}

// ---------------- host ------------------------------------------------------
extern "C" void kernel_launch(void* const* d_in, const int* in_sizes, int n_in,
                              void* d_out, int out_size) {
    const float* enc_key = (const float*)d_in[0];
    const float* enc_val = (const float*)d_in[1];
    const int*   mask    = (const int*)d_in[2];
    const float* emb     = (const float*)d_in[3];
    const float* w_ih1   = (const float*)d_in[4];
    const float* w_hh1   = (const float*)d_in[5];
    const float* b_ih1   = (const float*)d_in[6];
    const float* b_hh1   = (const float*)d_in[7];
    const float* w_ih2   = (const float*)d_in[8];
    const float* w_hh2   = (const float*)d_in[9];
    const float* b_ih2   = (const float*)d_in[10];
    const float* b_hh2   = (const float*)d_in[11];
    const float* wq      = (const float*)d_in[12];
    const float* bq      = (const float*)d_in[13];
    const float* wp      = (const float*)d_in[14];
    const float* bp      = (const float*)d_in[15];
    float* out = (float*)d_out;

    static int s_attr_done = 0;
    if (!s_attr_done) {
        cudaFuncSetAttribute(k_lstm1, cudaFuncAttributeMaxDynamicSharedMemorySize, L1_SMEM);
        cudaFuncSetAttribute(k_lstm2, cudaFuncAttributeMaxDynamicSharedMemorySize, L2_SMEM);
        cudaFuncSetAttribute(k_pred,  cudaFuncAttributeMaxDynamicSharedMemorySize, KP_SMEM);
        s_attr_done = 1;
    }

    k_prep_small<<<640, 256>>>(w_ih1, w_hh1, b_ih1, b_hh1,
                               w_ih2, w_hh2, b_ih2, b_hh2, wq);
    k_prep_wp<<<dim3(316, 4), 256>>>(wp);
    k_init<<<128, 256>>>();
    for (int s = 0; s < ML; s++) {
        int p = s & 1;
        k_lstm1<<<dim3(8, 16), 512, L1_SMEM>>>(emb, p);
        k_lstm2<<<dim3(4, 16), 512, L2_SMEM>>>(p);
        k_attn<<<256, 256>>>(enc_key, enc_val, mask, bq);
        k_pred<<<dim3(79, 8), 512, KP_SMEM>>>(bp, out, s);
    }
}

// round 16
// speedup vs baseline: 1.1129x; 1.1129x over previous
#include <cuda_runtime.h>

#define Bn   256
#define Tn   512
#define Dn   64
#define En   128
#define H1n  128
#define H2n  64
#define Vn   10000
#define ML   30
#define SOS_ 1
#define EOS_ 2

typedef unsigned long long ull;

// ---------------- persistent state + prepped weights (device globals) -------
__device__ float g_h1[2][Bn * H1n];        // ping-pong
__device__ float g_c1[Bn * H1n];
__device__ float g_h2[2][Bn * H2n];        // ping-pong
__device__ float g_c2[Bn * H2n];
__device__ float g_x[Bn * 128];            // [h2(64) | ctx(64)] pred input
__device__ ull   g_amax[Bn];               // packed (fkey(val)<<32 | ~v)

// per-block contiguous, gate-interleaved weight slices
__device__ float g_w1B[8][320][64];        // [rowtile][k][row-in-tile]
__device__ float g_w2B[4][192][64];
__device__ float g_wpB[79][128][128];      // [vtile][k][v-in-tile], zero-padded
__device__ float g_b1R[512];
__device__ float g_b2R[256];
__device__ float g_wqT[64 * 64];           // [k][d]

__device__ __forceinline__ unsigned int fkey(float f) {
    unsigned int u = __float_as_uint(f);
    return (u & 0x80000000u) ? ~u : (u | 0x80000000u);
}
__device__ __forceinline__ float sigm(float x) { return 1.0f / (1.0f + expf(-x)); }

__device__ __forceinline__ void fma2(ull& d, ull a, ull b) {
    asm("fma.rn.f32x2 %0, %1, %2, %0;" : "+l"(d) : "l"(a), "l"(b));
}
__device__ __forceinline__ void add2(ull& d, ull a) {
    asm("add.rn.f32x2 %0, %0, %1;" : "+l"(d) : "l"(a));
}
__device__ __forceinline__ ull dup2(float x) {
    unsigned int u = __float_as_uint(x); ull r;
    asm("mov.b64 %0, {%1, %1};" : "=l"(r) : "r"(u));
    return r;
}
__device__ __forceinline__ void unpk2(ull a, float& lo, float& hi) {
    unsigned int ul, uh;
    asm("mov.b64 {%0, %1}, %2;" : "=r"(ul), "=r"(uh) : "l"(a));
    lo = __uint_as_float(ul); hi = __uint_as_float(uh);
}
__device__ __forceinline__ void cpa16(void* s, const void* g) {
    unsigned sa = (unsigned)__cvta_generic_to_shared(s);
    asm volatile("cp.async.cg.shared.global [%0], [%1], 16;" :: "r"(sa), "l"(g));
}
#define CP_COMMIT()  asm volatile("cp.async.commit_group;")
#define CP_WAIT0()   asm volatile("cp.async.wait_group 0;")

// ---------------- one-time prep ---------------------------------------------
__global__ void k_prep_small(const float* __restrict__ wih1, const float* __restrict__ whh1,
                             const float* __restrict__ bih1, const float* __restrict__ bhh1,
                             const float* __restrict__ wih2, const float* __restrict__ whh2,
                             const float* __restrict__ bih2, const float* __restrict__ bhh2,
                             const float* __restrict__ wq) {
    int n = blockDim.x * gridDim.x;
    int t0 = blockIdx.x * blockDim.x + threadIdx.x;
    for (int i = t0; i < 8 * 320 * 64; i += n) {
        int rt = i / (320 * 64), rem = i - rt * 320 * 64;
        int k = rem >> 6, j = rem & 63;
        int c = rt * 64 + j;
        int h = c >> 2, g = c & 3, r = g * 128 + h;
        ((float*)g_w1B)[i] = (k < 192) ? wih1[r * 192 + k] : whh1[r * 128 + (k - 192)];
    }
    for (int i = t0; i < 4 * 192 * 64; i += n) {
        int rt = i / (192 * 64), rem = i - rt * 192 * 64;
        int k = rem >> 6, j = rem & 63;
        int c = rt * 64 + j;
        int h = c >> 2, g = c & 3, r = g * 64 + h;
        ((float*)g_w2B)[i] = (k < 128) ? wih2[r * 128 + k] : whh2[r * 64 + (k - 128)];
    }
    for (int i = t0; i < 64 * 64; i += n) {
        int k = i >> 6, d = i & 63;
        g_wqT[i] = wq[d * 64 + k];
    }
    for (int c = t0; c < 512; c += n) {
        int h = c >> 2, g = c & 3, r = g * 128 + h;
        g_b1R[c] = bih1[r] + bhh1[r];
    }
    for (int c = t0; c < 256; c += n) {
        int h = c >> 2, g = c & 3, r = g * 64 + h;
        g_b2R[c] = bih2[r] + bhh2[r];
    }
}

// tiled transpose wp[10000][128] -> g_wpB[79][128][128] (zero-padded)
__global__ void k_prep_wp(const float* __restrict__ wp) {
    __shared__ float t[32][33];
    int v0 = blockIdx.x * 32, kt = blockIdx.y * 32;
    int tx = threadIdx.x & 31, ty = threadIdx.x >> 5;   // 32 x 8
    #pragma unroll
    for (int i = 0; i < 4; i++) {
        int v = v0 + ty + i * 8;
        t[ty + i * 8][tx] = (v < Vn) ? wp[(size_t)v * 128 + kt + tx] : 0.f;
    }
    __syncthreads();
    int v = v0 + tx;
    #pragma unroll
    for (int i = 0; i < 4; i++) {
        int k = kt + ty + i * 8;
        g_wpB[v >> 7][k][v & 127] = t[tx][ty + i * 8];
    }
}

__global__ void k_init() {
    int i = blockIdx.x * blockDim.x + threadIdx.x;
    if (i < Bn * H1n) { g_h1[0][i] = 0.f; g_h1[1][i] = 0.f; g_c1[i] = 0.f; }
    if (i < Bn * H2n) { g_h2[0][i] = 0.f; g_h2[1][i] = 0.f; g_c2[i] = 0.f; }
    if (i < Bn * 128) g_x[i] = 0.f;
    if (i < Bn) g_amax[i] = (ull)(~(unsigned int)SOS_);
}

// ---------------- k_lstm1: grid (8 rowtiles, 16 btiles), 512 thr (R13) ------
#define L1_TOK   0
#define L1_SW    128                                // [320][64] f  = 81920
#define L1_SXD   (128 + 81920)                      // [320][18] ull = 46080
#define L1_SR    (L1_SXD + 46080)                   // [3][128][4] ull = 12288
#define L1_SG    (L1_SR + 12288)                    // [64][18] f   = 4608
#define L1_SMEM  (L1_SG + 4608)

__global__ void __launch_bounds__(512) k_lstm1(const float* __restrict__ emb, int p) {
    extern __shared__ __align__(16) char sm[];
    int*  s_tok       = (int*)(sm + L1_TOK);
    float (*s_w)[64]  = (float(*)[64])(sm + L1_SW);
    ull   (*s_xd)[18] = (ull(*)[18])(sm + L1_SXD);
    ull   (*s_r)[128][4] = (ull(*)[128][4])(sm + L1_SR);
    float (*s_g)[18]  = (float(*)[18])(sm + L1_SG);

    const int tid = threadIdx.x;
    const int rt = blockIdx.x, bt = blockIdx.y;
    const int r0 = rt * 64, b0 = bt * 16;
    const float* __restrict__ h1old = g_h1[p];
    float* __restrict__ h1new = g_h1[p ^ 1];

    {
        const float* src = &g_w1B[rt][0][0];
        #pragma unroll
        for (int i = 0; i < 10; i++) {
            int idx = tid + i * 512;
            cpa16((char*)&s_w[0][0] + idx * 16, src + idx * 4);
        }
    }
    CP_COMMIT();

    if (tid < 16) {
        ull a = g_amax[b0 + tid];
        s_tok[tid] = (int)(~(unsigned int)(a & 0xFFFFFFFFull));
    }
    __syncthreads();

    for (int i = 0; i < 10; i++) {
        int idx = tid + i * 512;
        int b = idx / 320, k = idx - b * 320;
        float v;
        if (k < 128) {
            int t = s_tok[b];
            v = (t == EOS_) ? 0.f : emb[(size_t)t * En + k];
        } else if (k < 192) {
            v = g_x[(b0 + b) * 128 + 64 + (k - 128)];
        } else {
            v = h1old[(b0 + b) * H1n + (k - 192)];
        }
        s_xd[k][b] = dup2(v);
    }
    CP_WAIT0();
    __syncthreads();

    const int kg = tid >> 7;
    const int t7 = tid & 127;
    const int RQ = t7 >> 3, Bg = t7 & 7;
    ull a00 = 0, a01 = 0, a10 = 0, a11 = 0;

    {
        const int k0 = kg * 80;
        #pragma unroll 8
        for (int kk = k0; kk < k0 + 80; kk++) {
            ulonglong2 w2 = *(const ulonglong2*)&s_w[kk][4 * RQ];
            ulonglong2 x2 = *(const ulonglong2*)&s_xd[kk][2 * Bg];
            fma2(a00, w2.x, x2.x); fma2(a01, w2.x, x2.y);
            fma2(a10, w2.y, x2.x); fma2(a11, w2.y, x2.y);
        }
    }

    if (kg > 0) {
        s_r[kg - 1][t7][0] = a00; s_r[kg - 1][t7][1] = a01;
        s_r[kg - 1][t7][2] = a10; s_r[kg - 1][t7][3] = a11;
    }
    __syncthreads();
    if (kg == 0) {
        #pragma unroll
        for (int j = 0; j < 3; j++) {
            add2(a00, s_r[j][t7][0]); add2(a01, s_r[j][t7][1]);
            add2(a10, s_r[j][t7][2]); add2(a11, s_r[j][t7][3]);
        }
        float b0v = g_b1R[r0 + 4 * RQ],     b1v = g_b1R[r0 + 4 * RQ + 1];
        float b2v = g_b1R[r0 + 4 * RQ + 2], b3v = g_b1R[r0 + 4 * RQ + 3];
        float v0, v1;
        unpk2(a00, v0, v1);
        s_g[4 * RQ][2 * Bg] = v0 + b0v; s_g[4 * RQ + 1][2 * Bg] = v1 + b1v;
        unpk2(a01, v0, v1);
        s_g[4 * RQ][2 * Bg + 1] = v0 + b0v; s_g[4 * RQ + 1][2 * Bg + 1] = v1 + b1v;
        unpk2(a10, v0, v1);
        s_g[4 * RQ + 2][2 * Bg] = v0 + b2v; s_g[4 * RQ + 3][2 * Bg] = v1 + b3v;
        unpk2(a11, v0, v1);
        s_g[4 * RQ + 2][2 * Bg + 1] = v0 + b2v; s_g[4 * RQ + 3][2 * Bg + 1] = v1 + b3v;
    }
    __syncthreads();

    if (tid < 256) {
        int b = tid & 15, hl = tid >> 4;
        float gi = s_g[4 * hl][b],     gf = s_g[4 * hl + 1][b];
        float gg = s_g[4 * hl + 2][b], go = s_g[4 * hl + 3][b];
        int gidx = (b0 + b) * H1n + rt * 16 + hl;
        float c = sigm(gf) * g_c1[gidx] + sigm(gi) * tanhf(gg);
        g_c1[gidx] = c;
        h1new[gidx] = sigm(go) * tanhf(c);
    }
}

// ---------------- k_lstm2: grid (4 rowtiles, 16 btiles), 512 thr (R13) ------
#define L2_SW    0                                  // [192][64] f  = 49152
#define L2_SXD   49152                              // [192][18] ull = 27648
#define L2_SR    (49152 + 27648)                    // [3][128][4] ull = 12288
#define L2_SG    (L2_SR + 12288)                    // 4608
#define L2_SMEM  (L2_SG + 4608)

__global__ void __launch_bounds__(512) k_lstm2(int p) {
    extern __shared__ __align__(16) char sm[];
    float (*s_w)[64]  = (float(*)[64])(sm + L2_SW);
    ull   (*s_xd)[18] = (ull(*)[18])(sm + L2_SXD);
    ull   (*s_r)[128][4] = (ull(*)[128][4])(sm + L2_SR);
    float (*s_g)[18]  = (float(*)[18])(sm + L2_SG);

    const int tid = threadIdx.x;
    const int rt = blockIdx.x, bt = blockIdx.y;
    const int r0 = rt * 64, b0 = bt * 16;
    const float* __restrict__ h1new = g_h1[p ^ 1];
    const float* __restrict__ h2old = g_h2[p];
    float* __restrict__ h2new = g_h2[p ^ 1];

    {
        const float* src = &g_w2B[rt][0][0];
        #pragma unroll
        for (int i = 0; i < 6; i++) {
            int idx = tid + i * 512;
            cpa16((char*)&s_w[0][0] + idx * 16, src + idx * 4);
        }
    }
    CP_COMMIT();

    for (int i = 0; i < 6; i++) {
        int idx = tid + i * 512;
        int b = idx / 192, k = idx - b * 192;
        float v = (k < 128) ? h1new[(b0 + b) * H1n + k]
                            : h2old[(b0 + b) * H2n + (k - 128)];
        s_xd[k][b] = dup2(v);
    }
    CP_WAIT0();
    __syncthreads();

    const int kg = tid >> 7;
    const int t7 = tid & 127;
    const int RQ = t7 >> 3, Bg = t7 & 7;
    ull a00 = 0, a01 = 0, a10 = 0, a11 = 0;

    {
        const int k0 = kg * 48;
        #pragma unroll 8
        for (int kk = k0; kk < k0 + 48; kk++) {
            ulonglong2 w2 = *(const ulonglong2*)&s_w[kk][4 * RQ];
            ulonglong2 x2 = *(const ulonglong2*)&s_xd[kk][2 * Bg];
            fma2(a00, w2.x, x2.x); fma2(a01, w2.x, x2.y);
            fma2(a10, w2.y, x2.x); fma2(a11, w2.y, x2.y);
        }
    }

    if (kg > 0) {
        s_r[kg - 1][t7][0] = a00; s_r[kg - 1][t7][1] = a01;
        s_r[kg - 1][t7][2] = a10; s_r[kg - 1][t7][3] = a11;
    }
    __syncthreads();
    if (kg == 0) {
        #pragma unroll
        for (int j = 0; j < 3; j++) {
            add2(a00, s_r[j][t7][0]); add2(a01, s_r[j][t7][1]);
            add2(a10, s_r[j][t7][2]); add2(a11, s_r[j][t7][3]);
        }
        float b0v = g_b2R[r0 + 4 * RQ],     b1v = g_b2R[r0 + 4 * RQ + 1];
        float b2v = g_b2R[r0 + 4 * RQ + 2], b3v = g_b2R[r0 + 4 * RQ + 3];
        float v0, v1;
        unpk2(a00, v0, v1);
        s_g[4 * RQ][2 * Bg] = v0 + b0v; s_g[4 * RQ + 1][2 * Bg] = v1 + b1v;
        unpk2(a01, v0, v1);
        s_g[4 * RQ][2 * Bg + 1] = v0 + b0v; s_g[4 * RQ + 1][2 * Bg + 1] = v1 + b1v;
        unpk2(a10, v0, v1);
        s_g[4 * RQ + 2][2 * Bg] = v0 + b2v; s_g[4 * RQ + 3][2 * Bg] = v1 + b3v;
        unpk2(a11, v0, v1);
        s_g[4 * RQ + 2][2 * Bg + 1] = v0 + b2v; s_g[4 * RQ + 3][2 * Bg + 1] = v1 + b3v;
    }
    __syncthreads();

    if (tid < 256) {
        int b = tid & 15, hl = tid >> 4;
        float gi = s_g[4 * hl][b],     gf = s_g[4 * hl + 1][b];
        float gg = s_g[4 * hl + 2][b], go = s_g[4 * hl + 3][b];
        int gidx = (b0 + b) * H2n + rt * 16 + hl;
        float c = sigm(gf) * g_c2[gidx] + sigm(gi) * tanhf(gg);
        g_c2[gidx] = c;
        float h = sigm(go) * tanhf(c);
        h2new[gidx] = h;
        g_x[(b0 + b) * 128 + rt * 16 + hl] = h;
    }
}

// ---------------- attention (unchanged) -------------------------------------
__global__ void __launch_bounds__(256) k_attn(
    const float* __restrict__ enc_key, const float* __restrict__ enc_val,
    const int* __restrict__ mask, const float* __restrict__ bq)
{
    __shared__ __align__(16) float s_q[64];
    __shared__ float s_h2[64];
    __shared__ float s_qp[4][64];
    __shared__ float s_e[512];
    __shared__ float s_w[512];
    __shared__ float s_red[40];
    __shared__ float s_p[4][64];
    const int b = blockIdx.x, tid = threadIdx.x;
    const int lane = tid & 31, warp = tid >> 5;

    if (tid == 0) g_amax[b] = 0ull;
    if (tid < 64) s_h2[tid] = g_x[b * 128 + tid];
    __syncthreads();

    {
        int d = tid & 63, kq = tid >> 6;
        float a = 0.f;
        #pragma unroll
        for (int k = kq * 16; k < kq * 16 + 16; k++)
            a += g_wqT[k * 64 + d] * s_h2[k];
        s_qp[kq][d] = a;
    }
    __syncthreads();
    if (tid < 64)
        s_q[tid] = s_qp[0][tid] + s_qp[1][tid] + s_qp[2][tid] + s_qp[3][tid] + bq[tid];
    __syncthreads();

    {
        const int slot = tid >> 2, dq = tid & 3;
        const float4* qp = (const float4*)(s_q + dq * 16);
        float4 q0 = qp[0], q1 = qp[1], q2 = qp[2], q3 = qp[3];
        #pragma unroll 4
        for (int i = 0; i < 8; i++) {
            int t = slot + 64 * i;
            const float4* kp = (const float4*)(enc_key + ((size_t)t * Bn + b) * Dn + dq * 16);
            float4 a = kp[0], c = kp[1], d = kp[2], e = kp[3];
            float pp = a.x * q0.x + a.y * q0.y + a.z * q0.z + a.w * q0.w
                     + c.x * q1.x + c.y * q1.y + c.z * q1.z + c.w * q1.w
                     + d.x * q2.x + d.y * q2.y + d.z * q2.z + d.w * q2.w
                     + e.x * q3.x + e.y * q3.y + e.z * q3.z + e.w * q3.w;
            pp += __shfl_xor_sync(0xffffffffu, pp, 1);
            pp += __shfl_xor_sync(0xffffffffu, pp, 2);
            if (dq == 0) s_e[t] = pp;
        }
    }
    __syncthreads();

    float e0 = s_e[tid], e1 = s_e[tid + 256];
    float mx = fmaxf(e0, e1);
    #pragma unroll
    for (int o = 16; o; o >>= 1) mx = fmaxf(mx, __shfl_xor_sync(0xffffffffu, mx, o));
    if (lane == 0) s_red[warp] = mx;
    __syncthreads();
    if (tid == 0) {
        float m = s_red[0];
        #pragma unroll
        for (int i = 1; i < 8; i++) m = fmaxf(m, s_red[i]);
        s_red[32] = m;
    }
    __syncthreads();
    mx = s_red[32];
    int m0 = mask[(size_t)b * Tn + tid], m1 = mask[(size_t)b * Tn + tid + 256];
    float x0 = expf(e0 - mx), x1 = expf(e1 - mx);
    float s = x0 + x1, ws = (m0 ? x0 : 0.f) + (m1 ? x1 : 0.f);
    #pragma unroll
    for (int o = 16; o; o >>= 1) {
        s  += __shfl_xor_sync(0xffffffffu, s,  o);
        ws += __shfl_xor_sync(0xffffffffu, ws, o);
    }
    if (lane == 0) { s_red[warp] = s; s_red[8 + warp] = ws; }
    __syncthreads();
    if (tid == 0) {
        float S = 0.f, W = 0.f;
        #pragma unroll
        for (int i = 0; i < 8; i++) { S += s_red[i]; W += s_red[8 + i]; }
        s_red[33] = 1.0f / (S * fmaxf(W / S, 2e-30f));
    }
    __syncthreads();
    float inv = s_red[33];
    s_w[tid]       = m0 ? x0 * inv : 0.f;
    s_w[tid + 256] = m1 ? x1 * inv : 0.f;
    __syncthreads();

    {
        int d = tid & 63, ch = tid >> 6;
        const float* vb = enc_val + (size_t)b * Dn + d;
        float a0 = 0.f, a1 = 0.f;
        #pragma unroll 4
        for (int t = ch * 128; t < ch * 128 + 128; t += 2) {
            a0 += s_w[t]     * vb[(size_t)t * (Bn * Dn)];
            a1 += s_w[t + 1] * vb[(size_t)(t + 1) * (Bn * Dn)];
        }
        s_p[ch][d] = a0 + a1;
    }
    __syncthreads();
    if (tid < 64) {
        float c = s_p[0][tid] + s_p[1][tid] + s_p[2][tid] + s_p[3][tid];
        g_x[b * 128 + 64 + tid] = c;
    }
}

// ---------------- pred GEMM: 8b thread tile, 4-way k-split, fused argmax ----
// grid (79, 8), 512 thr: lane=vq(4v), (tid>>5)&3=bg(8b), tid>>7=kg(32k).
#define KP_SWT   0                                  // [128][128] f  = 65536
#define KP_SXD   65536                              // [128][34] ull = 34816
#define KP_SMEM  (65536 + 34816)

__global__ void __launch_bounds__(512, 2) k_pred(const float* __restrict__ bp,
                                                 float* __restrict__ out, int step) {
    extern __shared__ __align__(16) char sm[];
    float (*s_wt)[128] = (float(*)[128])(sm + KP_SWT);
    ull   (*s_xd)[34]  = (ull(*)[34])(sm + KP_SXD);     // [k][b] dup pairs
    ull   (*s_pp)[17]  = (ull(*)[17])(sm + KP_SWT);     // partials (reuse s_wt)
    const int tid = threadIdx.x;
    const int b0 = blockIdx.y * 32;
    const int vt = blockIdx.x;

    // stage all 128 weight rows (contiguous zero-padded slice, no guards)
    {
        const float* src = &g_wpB[vt][0][0];
        #pragma unroll
        for (int i = 0; i < 8; i++) {
            int idx = tid + i * 512;                // 4096 float4 slots
            cpa16((char*)&s_wt[0][0] + idx * 16, src + idx * 4);
        }
    }
    CP_COMMIT();

    // x fill: coalesced LDG (b-major index), transposed STS to [k][b]
    for (int i = 0; i < 8; i++) {
        int idx = tid + i * 512;                // 4096 elements
        int b = idx >> 7, k = idx & 127;
        s_xd[k][b] = dup2(g_x[(b0 + b) * 128 + k]);
    }
    CP_WAIT0();
    __syncthreads();

    const int vq = tid & 31;
    const int bg = (tid >> 5) & 3;
    const int kg = tid >> 7;
    const int t7 = tid & 127;
    const int bb = bg * 8;
    const int v0 = vt * 128 + vq * 4;
    const bool vok = (v0 + 3) < Vn;

    ull acc0[8] = {}, acc1[8] = {};          // acc0:(v0,v0+1) acc1:(v0+2,v0+3) x 8 b
    {
        const int k0 = kg * 32;
        #pragma unroll 4
        for (int kk = k0; kk < k0 + 32; kk++) {
            ulonglong2 w  = *(const ulonglong2*)&s_wt[kk][vq * 4];
            ulonglong2 xa = *(const ulonglong2*)&s_xd[kk][bb];
            ulonglong2 xb = *(const ulonglong2*)&s_xd[kk][bb + 2];
            ulonglong2 xc = *(const ulonglong2*)&s_xd[kk][bb + 4];
            ulonglong2 xe = *(const ulonglong2*)&s_xd[kk][bb + 6];
            fma2(acc0[0], w.x, xa.x); fma2(acc0[1], w.x, xa.y);
            fma2(acc0[2], w.x, xb.x); fma2(acc0[3], w.x, xb.y);
            fma2(acc0[4], w.x, xc.x); fma2(acc0[5], w.x, xc.y);
            fma2(acc0[6], w.x, xe.x); fma2(acc0[7], w.x, xe.y);
            fma2(acc1[0], w.y, xa.x); fma2(acc1[1], w.y, xa.y);
            fma2(acc1[2], w.y, xb.x); fma2(acc1[3], w.y, xb.y);
            fma2(acc1[4], w.y, xc.x); fma2(acc1[5], w.y, xc.y);
            fma2(acc1[6], w.y, xe.x); fma2(acc1[7], w.y, xe.y);
        }
    }

    __syncthreads();                          // all s_wt reads done; safe to reuse
    if (kg > 0) {
        int row = (kg - 1) * 128 + t7;
        #pragma unroll
        for (int j = 0; j < 8; j++) {
            s_pp[row][j]     = acc0[j];
            s_pp[row][8 + j] = acc1[j];
        }
    }
    __syncthreads();
    if (kg == 0) {
        #pragma unroll
        for (int jj = 0; jj < 3; jj++) {
            int row = jj * 128 + t7;
            #pragma unroll
            for (int j = 0; j < 8; j++) {
                add2(acc0[j], s_pp[row][j]);
                add2(acc1[j], s_pp[row][8 + j]);
            }
        }
        float bs0 = 0.f, bs1 = 0.f, bs2 = 0.f, bs3 = 0.f;
        if (vok) {
            float4 b4 = *(const float4*)&bp[v0];
            bs0 = b4.x; bs1 = b4.y; bs2 = b4.z; bs3 = b4.w;
        }
        #pragma unroll
        for (int j = 0; j < 8; j++) {
            int bi = b0 + bb + j;
            float r0, r1, r2, r3;
            unpk2(acc0[j], r0, r1);
            unpk2(acc1[j], r2, r3);
            r0 += bs0; r1 += bs1; r2 += bs2; r3 += bs3;
            if (vok) {
                __stcs((float4*)(out + (size_t)bi * (ML * Vn) + (size_t)step * Vn + v0),
                       make_float4(r0, r1, r2, r3));
            }
            float best = r0; int bv = v0;
            if (r1 > best) { best = r1; bv = v0 + 1; }
            if (r2 > best) { best = r2; bv = v0 + 2; }
            if (r3 > best) { best = r3; bv = v0 + 3; }
            ull pk = vok ? (((ull)fkey(best) << 32) | (unsigned int)(~bv)) : 0ull;
            #pragma unroll
            for (int o = 16; o; o >>= 1) {
                ull other = __shfl_down_sync(0xffffffffu, pk, o);
                if (other > pk) pk = other;
            }
            if (vq == 0) atomicMax(&g_amax[bi], pk);
        }
    }
}

// ---------------- host ------------------------------------------------------
extern "C" void kernel_launch(void* const* d_in, const int* in_sizes, int n_in,
                              void* d_out, int out_size) {
    const float* enc_key = (const float*)d_in[0];
    const float* enc_val = (const float*)d_in[1];
    const int*   mask    = (const int*)d_in[2];
    const float* emb     = (const float*)d_in[3];
    const float* w_ih1   = (const float*)d_in[4];
    const float* w_hh1   = (const float*)d_in[5];
    const float* b_ih1   = (const float*)d_in[6];
    const float* b_hh1   = (const float*)d_in[7];
    const float* w_ih2   = (const float*)d_in[8];
    const float* w_hh2   = (const float*)d_in[9];
    const float* b_ih2   = (const float*)d_in[10];
    const float* b_hh2   = (const float*)d_in[11];
    const float* wq      = (const float*)d_in[12];
    const float* bq      = (const float*)d_in[13];
    const float* wp      = (const float*)d_in[14];
    const float* bp      = (const float*)d_in[15];
    float* out = (float*)d_out;

    static int s_attr_done = 0;
    if (!s_attr_done) {
        cudaFuncSetAttribute(k_lstm1, cudaFuncAttributeMaxDynamicSharedMemorySize, L1_SMEM);
        cudaFuncSetAttribute(k_lstm2, cudaFuncAttributeMaxDynamicSharedMemorySize, L2_SMEM);
        cudaFuncSetAttribute(k_pred,  cudaFuncAttributeMaxDynamicSharedMemorySize, KP_SMEM);
        s_attr_done = 1;
    }

    k_prep_small<<<640, 256>>>(w_ih1, w_hh1, b_ih1, b_hh1,
                               w_ih2, w_hh2, b_ih2, b_hh2, wq);
    k_prep_wp<<<dim3(316, 4), 256>>>(wp);
    k_init<<<128, 256>>>();
    for (int s = 0; s < ML; s++) {
        int p = s & 1;
        k_lstm1<<<dim3(8, 16), 512, L1_SMEM>>>(emb, p);
        k_lstm2<<<dim3(4, 16), 512, L2_SMEM>>>(p);
        k_attn<<<256, 256>>>(enc_key, enc_val, mask, bq);
        k_pred<<<dim3(79, 8), 512, KP_SMEM>>>(bp, out, s);
    }
}

// round 17
// speedup vs baseline: 1.1299x; 1.0152x over previous
#include <cuda_runtime.h>

#define Bn   256
#define Tn   512
#define Dn   64
#define En   128
#define H1n  128
#define H2n  64
#define Vn   10000
#define ML   30
#define SOS_ 1
#define EOS_ 2

typedef unsigned long long ull;

// ---------------- persistent state + prepped weights (device globals) -------
__device__ float g_h1[2][Bn * H1n];        // ping-pong
__device__ float g_c1[Bn * H1n];
__device__ float g_h2[2][Bn * H2n];        // ping-pong
__device__ float g_c2[Bn * H2n];
__device__ float g_x[Bn * 128];            // [h2(64) | ctx(64)] pred input
__device__ ull   g_amax[Bn];               // packed (fkey(val)<<32 | ~v)

// per-block contiguous, gate-interleaved weight slices
__device__ float g_w1B[8][320][64];        // [rowtile][k][row-in-tile]
__device__ float g_w2B[4][192][64];
__device__ float g_wpB[79][128][128];      // [vtile][k][v-in-tile], zero-padded
__device__ float g_b1R[512];
__device__ float g_b2R[256];
__device__ float g_wqT[64 * 64];           // [k][d]

__device__ __forceinline__ unsigned int fkey(float f) {
    unsigned int u = __float_as_uint(f);
    return (u & 0x80000000u) ? ~u : (u | 0x80000000u);
}
__device__ __forceinline__ float sigm(float x) { return 1.0f / (1.0f + expf(-x)); }

__device__ __forceinline__ void fma2(ull& d, ull a, ull b) {
    asm("fma.rn.f32x2 %0, %1, %2, %0;" : "+l"(d) : "l"(a), "l"(b));
}
__device__ __forceinline__ void add2(ull& d, ull a) {
    asm("add.rn.f32x2 %0, %0, %1;" : "+l"(d) : "l"(a));
}
__device__ __forceinline__ ull dup2(float x) {
    unsigned int u = __float_as_uint(x); ull r;
    asm("mov.b64 %0, {%1, %1};" : "=l"(r) : "r"(u));
    return r;
}
__device__ __forceinline__ void unpk2(ull a, float& lo, float& hi) {
    unsigned int ul, uh;
    asm("mov.b64 {%0, %1}, %2;" : "=r"(ul), "=r"(uh) : "l"(a));
    lo = __uint_as_float(ul); hi = __uint_as_float(uh);
}
__device__ __forceinline__ void cpa16(void* s, const void* g) {
    unsigned sa = (unsigned)__cvta_generic_to_shared(s);
    asm volatile("cp.async.cg.shared.global [%0], [%1], 16;" :: "r"(sa), "l"(g));
}
#define CP_COMMIT()  asm volatile("cp.async.commit_group;")
#define CP_WAIT0()   asm volatile("cp.async.wait_group 0;")

// ---------------- one-time prep ---------------------------------------------
__global__ void k_prep_small(const float* __restrict__ wih1, const float* __restrict__ whh1,
                             const float* __restrict__ bih1, const float* __restrict__ bhh1,
                             const float* __restrict__ wih2, const float* __restrict__ whh2,
                             const float* __restrict__ bih2, const float* __restrict__ bhh2,
                             const float* __restrict__ wq) {
    int n = blockDim.x * gridDim.x;
    int t0 = blockIdx.x * blockDim.x + threadIdx.x;
    for (int i = t0; i < 8 * 320 * 64; i += n) {
        int rt = i / (320 * 64), rem = i - rt * 320 * 64;
        int k = rem >> 6, j = rem & 63;
        int c = rt * 64 + j;
        int h = c >> 2, g = c & 3, r = g * 128 + h;
        ((float*)g_w1B)[i] = (k < 192) ? wih1[r * 192 + k] : whh1[r * 128 + (k - 192)];
    }
    for (int i = t0; i < 4 * 192 * 64; i += n) {
        int rt = i / (192 * 64), rem = i - rt * 192 * 64;
        int k = rem >> 6, j = rem & 63;
        int c = rt * 64 + j;
        int h = c >> 2, g = c & 3, r = g * 64 + h;
        ((float*)g_w2B)[i] = (k < 128) ? wih2[r * 128 + k] : whh2[r * 64 + (k - 128)];
    }
    for (int i = t0; i < 64 * 64; i += n) {
        int k = i >> 6, d = i & 63;
        g_wqT[i] = wq[d * 64 + k];
    }
    for (int c = t0; c < 512; c += n) {
        int h = c >> 2, g = c & 3, r = g * 128 + h;
        g_b1R[c] = bih1[r] + bhh1[r];
    }
    for (int c = t0; c < 256; c += n) {
        int h = c >> 2, g = c & 3, r = g * 64 + h;
        g_b2R[c] = bih2[r] + bhh2[r];
    }
}

// tiled transpose wp[10000][128] -> g_wpB[79][128][128] (zero-padded)
__global__ void k_prep_wp(const float* __restrict__ wp) {
    __shared__ float t[32][33];
    int v0 = blockIdx.x * 32, kt = blockIdx.y * 32;
    int tx = threadIdx.x & 31, ty = threadIdx.x >> 5;   // 32 x 8
    #pragma unroll
    for (int i = 0; i < 4; i++) {
        int v = v0 + ty + i * 8;
        t[ty + i * 8][tx] = (v < Vn) ? wp[(size_t)v * 128 + kt + tx] : 0.f;
    }
    __syncthreads();
    int v = v0 + tx;
    #pragma unroll
    for (int i = 0; i < 4; i++) {
        int k = kt + ty + i * 8;
        g_wpB[v >> 7][k][v & 127] = t[tx][ty + i * 8];
    }
}

__global__ void k_init() {
    int i = blockIdx.x * blockDim.x + threadIdx.x;
    if (i < Bn * H1n) { g_h1[0][i] = 0.f; g_h1[1][i] = 0.f; g_c1[i] = 0.f; }
    if (i < Bn * H2n) { g_h2[0][i] = 0.f; g_h2[1][i] = 0.f; g_c2[i] = 0.f; }
    if (i < Bn * 128) g_x[i] = 0.f;
    if (i < Bn) g_amax[i] = (ull)(~(unsigned int)SOS_);
}

// ---------------- k_lstm1: grid (8 rowtiles, 16 btiles), 512 thr (R13) ------
#define L1_TOK   0
#define L1_SW    128                                // [320][64] f  = 81920
#define L1_SXD   (128 + 81920)                      // [320][18] ull = 46080
#define L1_SR    (L1_SXD + 46080)                   // [3][128][4] ull = 12288
#define L1_SG    (L1_SR + 12288)                    // [64][18] f   = 4608
#define L1_SMEM  (L1_SG + 4608)

__global__ void __launch_bounds__(512) k_lstm1(const float* __restrict__ emb, int p) {
    extern __shared__ __align__(16) char sm[];
    int*  s_tok       = (int*)(sm + L1_TOK);
    float (*s_w)[64]  = (float(*)[64])(sm + L1_SW);
    ull   (*s_xd)[18] = (ull(*)[18])(sm + L1_SXD);
    ull   (*s_r)[128][4] = (ull(*)[128][4])(sm + L1_SR);
    float (*s_g)[18]  = (float(*)[18])(sm + L1_SG);

    const int tid = threadIdx.x;
    const int rt = blockIdx.x, bt = blockIdx.y;
    const int r0 = rt * 64, b0 = bt * 16;
    const float* __restrict__ h1old = g_h1[p];
    float* __restrict__ h1new = g_h1[p ^ 1];

    {
        const float* src = &g_w1B[rt][0][0];
        #pragma unroll
        for (int i = 0; i < 10; i++) {
            int idx = tid + i * 512;
            cpa16((char*)&s_w[0][0] + idx * 16, src + idx * 4);
        }
    }
    CP_COMMIT();

    if (tid < 16) {
        ull a = g_amax[b0 + tid];
        s_tok[tid] = (int)(~(unsigned int)(a & 0xFFFFFFFFull));
    }
    __syncthreads();

    for (int i = 0; i < 10; i++) {
        int idx = tid + i * 512;
        int b = idx / 320, k = idx - b * 320;
        float v;
        if (k < 128) {
            int t = s_tok[b];
            v = (t == EOS_) ? 0.f : emb[(size_t)t * En + k];
        } else if (k < 192) {
            v = g_x[(b0 + b) * 128 + 64 + (k - 128)];
        } else {
            v = h1old[(b0 + b) * H1n + (k - 192)];
        }
        s_xd[k][b] = dup2(v);
    }
    CP_WAIT0();
    __syncthreads();

    const int kg = tid >> 7;
    const int t7 = tid & 127;
    const int RQ = t7 >> 3, Bg = t7 & 7;
    ull a00 = 0, a01 = 0, a10 = 0, a11 = 0;

    {
        const int k0 = kg * 80;
        #pragma unroll 8
        for (int kk = k0; kk < k0 + 80; kk++) {
            ulonglong2 w2 = *(const ulonglong2*)&s_w[kk][4 * RQ];
            ulonglong2 x2 = *(const ulonglong2*)&s_xd[kk][2 * Bg];
            fma2(a00, w2.x, x2.x); fma2(a01, w2.x, x2.y);
            fma2(a10, w2.y, x2.x); fma2(a11, w2.y, x2.y);
        }
    }

    if (kg > 0) {
        s_r[kg - 1][t7][0] = a00; s_r[kg - 1][t7][1] = a01;
        s_r[kg - 1][t7][2] = a10; s_r[kg - 1][t7][3] = a11;
    }
    __syncthreads();
    if (kg == 0) {
        #pragma unroll
        for (int j = 0; j < 3; j++) {
            add2(a00, s_r[j][t7][0]); add2(a01, s_r[j][t7][1]);
            add2(a10, s_r[j][t7][2]); add2(a11, s_r[j][t7][3]);
        }
        float b0v = g_b1R[r0 + 4 * RQ],     b1v = g_b1R[r0 + 4 * RQ + 1];
        float b2v = g_b1R[r0 + 4 * RQ + 2], b3v = g_b1R[r0 + 4 * RQ + 3];
        float v0, v1;
        unpk2(a00, v0, v1);
        s_g[4 * RQ][2 * Bg] = v0 + b0v; s_g[4 * RQ + 1][2 * Bg] = v1 + b1v;
        unpk2(a01, v0, v1);
        s_g[4 * RQ][2 * Bg + 1] = v0 + b0v; s_g[4 * RQ + 1][2 * Bg + 1] = v1 + b1v;
        unpk2(a10, v0, v1);
        s_g[4 * RQ + 2][2 * Bg] = v0 + b2v; s_g[4 * RQ + 3][2 * Bg] = v1 + b3v;
        unpk2(a11, v0, v1);
        s_g[4 * RQ + 2][2 * Bg + 1] = v0 + b2v; s_g[4 * RQ + 3][2 * Bg + 1] = v1 + b3v;
    }
    __syncthreads();

    if (tid < 256) {
        int b = tid & 15, hl = tid >> 4;
        float gi = s_g[4 * hl][b],     gf = s_g[4 * hl + 1][b];
        float gg = s_g[4 * hl + 2][b], go = s_g[4 * hl + 3][b];
        int gidx = (b0 + b) * H1n + rt * 16 + hl;
        float c = sigm(gf) * g_c1[gidx] + sigm(gi) * tanhf(gg);
        g_c1[gidx] = c;
        h1new[gidx] = sigm(go) * tanhf(c);
    }
}

// ---------------- k_lstm2: grid (4 rowtiles, 32 btiles of 8), 256 thr -------
#define L2_SW    0                                  // [192][64] f  = 49152
#define L2_SXD   49152                              // [192][10] ull = 15360
#define L2_SR    (49152 + 15360)                    // [3][64][4] ull = 6144
#define L2_SG    (L2_SR + 6144)                     // [64][10] f   = 2560
#define L2_SMEM  (L2_SG + 2560)

__global__ void __launch_bounds__(256) k_lstm2(int p) {
    extern __shared__ __align__(16) char sm[];
    float (*s_w)[64]  = (float(*)[64])(sm + L2_SW);
    ull   (*s_xd)[10] = (ull(*)[10])(sm + L2_SXD);
    ull   (*s_r)[64][4] = (ull(*)[64][4])(sm + L2_SR);
    float (*s_g)[10]  = (float(*)[10])(sm + L2_SG);

    const int tid = threadIdx.x;
    const int rt = blockIdx.x, bt = blockIdx.y;
    const int r0 = rt * 64, b0 = bt * 8;
    const float* __restrict__ h1new = g_h1[p ^ 1];
    const float* __restrict__ h2old = g_h2[p];
    float* __restrict__ h2new = g_h2[p ^ 1];

    {
        const float* src = &g_w2B[rt][0][0];
        #pragma unroll
        for (int i = 0; i < 12; i++) {
            int idx = tid + i * 256;                // 3072 float4 slots
            cpa16((char*)&s_w[0][0] + idx * 16, src + idx * 4);
        }
    }
    CP_COMMIT();

    for (int i = 0; i < 6; i++) {
        int idx = tid + i * 256;                // 1536 elements
        int b = idx / 192, k = idx - b * 192;
        float v = (k < 128) ? h1new[(b0 + b) * H1n + k]
                            : h2old[(b0 + b) * H2n + (k - 128)];
        s_xd[k][b] = dup2(v);
    }
    CP_WAIT0();
    __syncthreads();

    const int kg = tid >> 6;                 // 4 quarters of 48 k
    const int t6 = tid & 63;
    const int RQ = t6 >> 2, Bg = t6 & 3;     // rows 4RQ..4RQ+3, b (2Bg,2Bg+1)
    ull a00 = 0, a01 = 0, a10 = 0, a11 = 0;

    {
        const int k0 = kg * 48;
        #pragma unroll 8
        for (int kk = k0; kk < k0 + 48; kk++) {
            ulonglong2 w2 = *(const ulonglong2*)&s_w[kk][4 * RQ];
            ulonglong2 x2 = *(const ulonglong2*)&s_xd[kk][2 * Bg];
            fma2(a00, w2.x, x2.x); fma2(a01, w2.x, x2.y);
            fma2(a10, w2.y, x2.x); fma2(a11, w2.y, x2.y);
        }
    }

    if (kg > 0) {
        s_r[kg - 1][t6][0] = a00; s_r[kg - 1][t6][1] = a01;
        s_r[kg - 1][t6][2] = a10; s_r[kg - 1][t6][3] = a11;
    }
    __syncthreads();
    if (kg == 0) {
        #pragma unroll
        for (int j = 0; j < 3; j++) {
            add2(a00, s_r[j][t6][0]); add2(a01, s_r[j][t6][1]);
            add2(a10, s_r[j][t6][2]); add2(a11, s_r[j][t6][3]);
        }
        float b0v = g_b2R[r0 + 4 * RQ],     b1v = g_b2R[r0 + 4 * RQ + 1];
        float b2v = g_b2R[r0 + 4 * RQ + 2], b3v = g_b2R[r0 + 4 * RQ + 3];
        float v0, v1;
        unpk2(a00, v0, v1);
        s_g[4 * RQ][2 * Bg] = v0 + b0v; s_g[4 * RQ + 1][2 * Bg] = v1 + b1v;
        unpk2(a01, v0, v1);
        s_g[4 * RQ][2 * Bg + 1] = v0 + b0v; s_g[4 * RQ + 1][2 * Bg + 1] = v1 + b1v;
        unpk2(a10, v0, v1);
        s_g[4 * RQ + 2][2 * Bg] = v0 + b2v; s_g[4 * RQ + 3][2 * Bg] = v1 + b3v;
        unpk2(a11, v0, v1);
        s_g[4 * RQ + 2][2 * Bg + 1] = v0 + b2v; s_g[4 * RQ + 3][2 * Bg + 1] = v1 + b3v;
    }
    __syncthreads();

    if (tid < 128) {
        int b = tid & 7, hl = tid >> 3;
        float gi = s_g[4 * hl][b],     gf = s_g[4 * hl + 1][b];
        float gg = s_g[4 * hl + 2][b], go = s_g[4 * hl + 3][b];
        int gidx = (b0 + b) * H2n + rt * 16 + hl;
        float c = sigm(gf) * g_c2[gidx] + sigm(gi) * tanhf(gg);
        g_c2[gidx] = c;
        float h = sigm(go) * tanhf(c);
        h2new[gidx] = h;
        g_x[(b0 + b) * 128 + rt * 16 + hl] = h;
    }
}

// ---------------- attention (unchanged) -------------------------------------
__global__ void __launch_bounds__(256) k_attn(
    const float* __restrict__ enc_key, const float* __restrict__ enc_val,
    const int* __restrict__ mask, const float* __restrict__ bq)
{
    __shared__ __align__(16) float s_q[64];
    __shared__ float s_h2[64];
    __shared__ float s_qp[4][64];
    __shared__ float s_e[512];
    __shared__ float s_w[512];
    __shared__ float s_red[40];
    __shared__ float s_p[4][64];
    const int b = blockIdx.x, tid = threadIdx.x;
    const int lane = tid & 31, warp = tid >> 5;

    if (tid == 0) g_amax[b] = 0ull;
    if (tid < 64) s_h2[tid] = g_x[b * 128 + tid];
    __syncthreads();

    {
        int d = tid & 63, kq = tid >> 6;
        float a = 0.f;
        #pragma unroll
        for (int k = kq * 16; k < kq * 16 + 16; k++)
            a += g_wqT[k * 64 + d] * s_h2[k];
        s_qp[kq][d] = a;
    }
    __syncthreads();
    if (tid < 64)
        s_q[tid] = s_qp[0][tid] + s_qp[1][tid] + s_qp[2][tid] + s_qp[3][tid] + bq[tid];
    __syncthreads();

    {
        const int slot = tid >> 2, dq = tid & 3;
        const float4* qp = (const float4*)(s_q + dq * 16);
        float4 q0 = qp[0], q1 = qp[1], q2 = qp[2], q3 = qp[3];
        #pragma unroll 4
        for (int i = 0; i < 8; i++) {
            int t = slot + 64 * i;
            const float4* kp = (const float4*)(enc_key + ((size_t)t * Bn + b) * Dn + dq * 16);
            float4 a = kp[0], c = kp[1], d = kp[2], e = kp[3];
            float pp = a.x * q0.x + a.y * q0.y + a.z * q0.z + a.w * q0.w
                     + c.x * q1.x + c.y * q1.y + c.z * q1.z + c.w * q1.w
                     + d.x * q2.x + d.y * q2.y + d.z * q2.z + d.w * q2.w
                     + e.x * q3.x + e.y * q3.y + e.z * q3.z + e.w * q3.w;
            pp += __shfl_xor_sync(0xffffffffu, pp, 1);
            pp += __shfl_xor_sync(0xffffffffu, pp, 2);
            if (dq == 0) s_e[t] = pp;
        }
    }
    __syncthreads();

    float e0 = s_e[tid], e1 = s_e[tid + 256];
    float mx = fmaxf(e0, e1);
    #pragma unroll
    for (int o = 16; o; o >>= 1) mx = fmaxf(mx, __shfl_xor_sync(0xffffffffu, mx, o));
    if (lane == 0) s_red[warp] = mx;
    __syncthreads();
    if (tid == 0) {
        float m = s_red[0];
        #pragma unroll
        for (int i = 1; i < 8; i++) m = fmaxf(m, s_red[i]);
        s_red[32] = m;
    }
    __syncthreads();
    mx = s_red[32];
    int m0 = mask[(size_t)b * Tn + tid], m1 = mask[(size_t)b * Tn + tid + 256];
    float x0 = expf(e0 - mx), x1 = expf(e1 - mx);
    float s = x0 + x1, ws = (m0 ? x0 : 0.f) + (m1 ? x1 : 0.f);
    #pragma unroll
    for (int o = 16; o; o >>= 1) {
        s  += __shfl_xor_sync(0xffffffffu, s,  o);
        ws += __shfl_xor_sync(0xffffffffu, ws, o);
    }
    if (lane == 0) { s_red[warp] = s; s_red[8 + warp] = ws; }
    __syncthreads();
    if (tid == 0) {
        float S = 0.f, W = 0.f;
        #pragma unroll
        for (int i = 0; i < 8; i++) { S += s_red[i]; W += s_red[8 + i]; }
        s_red[33] = 1.0f / (S * fmaxf(W / S, 2e-30f));
    }
    __syncthreads();
    float inv = s_red[33];
    s_w[tid]       = m0 ? x0 * inv : 0.f;
    s_w[tid + 256] = m1 ? x1 * inv : 0.f;
    __syncthreads();

    {
        int d = tid & 63, ch = tid >> 6;
        const float* vb = enc_val + (size_t)b * Dn + d;
        float a0 = 0.f, a1 = 0.f;
        #pragma unroll 4
        for (int t = ch * 128; t < ch * 128 + 128; t += 2) {
            a0 += s_w[t]     * vb[(size_t)t * (Bn * Dn)];
            a1 += s_w[t + 1] * vb[(size_t)(t + 1) * (Bn * Dn)];
        }
        s_p[ch][d] = a0 + a1;
    }
    __syncthreads();
    if (tid < 64) {
        float c = s_p[0][tid] + s_p[1][tid] + s_p[2][tid] + s_p[3][tid];
        g_x[b * 128 + 64 + tid] = c;
    }
}

// ---------------- pred GEMM: 8b thread tile, 4-way k-split (R16) ------------
#define KP_SWT   0                                  // [128][128] f  = 65536
#define KP_SXD   65536                              // [128][34] ull = 34816
#define KP_SMEM  (65536 + 34816)

__global__ void __launch_bounds__(512, 2) k_pred(const float* __restrict__ bp,
                                                 float* __restrict__ out, int step) {
    extern __shared__ __align__(16) char sm[];
    float (*s_wt)[128] = (float(*)[128])(sm + KP_SWT);
    ull   (*s_xd)[34]  = (ull(*)[34])(sm + KP_SXD);     // [k][b] dup pairs
    ull   (*s_pp)[17]  = (ull(*)[17])(sm + KP_SWT);     // partials (reuse s_wt)
    const int tid = threadIdx.x;
    const int b0 = blockIdx.y * 32;
    const int vt = blockIdx.x;

    {
        const float* src = &g_wpB[vt][0][0];
        #pragma unroll
        for (int i = 0; i < 8; i++) {
            int idx = tid + i * 512;                // 4096 float4 slots
            cpa16((char*)&s_wt[0][0] + idx * 16, src + idx * 4);
        }
    }
    CP_COMMIT();

    for (int i = 0; i < 8; i++) {
        int idx = tid + i * 512;                // 4096 elements
        int b = idx >> 7, k = idx & 127;
        s_xd[k][b] = dup2(g_x[(b0 + b) * 128 + k]);
    }
    CP_WAIT0();
    __syncthreads();

    const int vq = tid & 31;
    const int bg = (tid >> 5) & 3;
    const int kg = tid >> 7;
    const int t7 = tid & 127;
    const int bb = bg * 8;
    const int v0 = vt * 128 + vq * 4;
    const bool vok = (v0 + 3) < Vn;

    ull acc0[8] = {}, acc1[8] = {};
    {
        const int k0 = kg * 32;
        #pragma unroll 4
        for (int kk = k0; kk < k0 + 32; kk++) {
            ulonglong2 w  = *(const ulonglong2*)&s_wt[kk][vq * 4];
            ulonglong2 xa = *(const ulonglong2*)&s_xd[kk][bb];
            ulonglong2 xb = *(const ulonglong2*)&s_xd[kk][bb + 2];
            ulonglong2 xc = *(const ulonglong2*)&s_xd[kk][bb + 4];
            ulonglong2 xe = *(const ulonglong2*)&s_xd[kk][bb + 6];
            fma2(acc0[0], w.x, xa.x); fma2(acc0[1], w.x, xa.y);
            fma2(acc0[2], w.x, xb.x); fma2(acc0[3], w.x, xb.y);
            fma2(acc0[4], w.x, xc.x); fma2(acc0[5], w.x, xc.y);
            fma2(acc0[6], w.x, xe.x); fma2(acc0[7], w.x, xe.y);
            fma2(acc1[0], w.y, xa.x); fma2(acc1[1], w.y, xa.y);
            fma2(acc1[2], w.y, xb.x); fma2(acc1[3], w.y, xb.y);
            fma2(acc1[4], w.y, xc.x); fma2(acc1[5], w.y, xc.y);
            fma2(acc1[6], w.y, xe.x); fma2(acc1[7], w.y, xe.y);
        }
    }

    __syncthreads();
    if (kg > 0) {
        int row = (kg - 1) * 128 + t7;
        #pragma unroll
        for (int j = 0; j < 8; j++) {
            s_pp[row][j]     = acc0[j];
            s_pp[row][8 + j] = acc1[j];
        }
    }
    __syncthreads();
    if (kg == 0) {
        #pragma unroll
        for (int jj = 0; jj < 3; jj++) {
            int row = jj * 128 + t7;
            #pragma unroll
            for (int j = 0; j < 8; j++) {
                add2(acc0[j], s_pp[row][j]);
                add2(acc1[j], s_pp[row][8 + j]);
            }
        }
        float bs0 = 0.f, bs1 = 0.f, bs2 = 0.f, bs3 = 0.f;
        if (vok) {
            float4 b4 = *(const float4*)&bp[v0];
            bs0 = b4.x; bs1 = b4.y; bs2 = b4.z; bs3 = b4.w;
        }
        #pragma unroll
        for (int j = 0; j < 8; j++) {
            int bi = b0 + bb + j;
            float r0, r1, r2, r3;
            unpk2(acc0[j], r0, r1);
            unpk2(acc1[j], r2, r3);
            r0 += bs0; r1 += bs1; r2 += bs2; r3 += bs3;
            if (vok) {
                __stcs((float4*)(out + (size_t)bi * (ML * Vn) + (size_t)step * Vn + v0),
                       make_float4(r0, r1, r2, r3));
            }
            float best = r0; int bv = v0;
            if (r1 > best) { best = r1; bv = v0 + 1; }
            if (r2 > best) { best = r2; bv = v0 + 2; }
            if (r3 > best) { best = r3; bv = v0 + 3; }
            ull pk = vok ? (((ull)fkey(best) << 32) | (unsigned int)(~bv)) : 0ull;
            #pragma unroll
            for (int o = 16; o; o >>= 1) {
                ull other = __shfl_down_sync(0xffffffffu, pk, o);
                if (other > pk) pk = other;
            }
            if (vq == 0) atomicMax(&g_amax[bi], pk);
        }
    }
}

// ---------------- host ------------------------------------------------------
extern "C" void kernel_launch(void* const* d_in, const int* in_sizes, int n_in,
                              void* d_out, int out_size) {
    const float* enc_key = (const float*)d_in[0];
    const float* enc_val = (const float*)d_in[1];
    const int*   mask    = (const int*)d_in[2];
    const float* emb     = (const float*)d_in[3];
    const float* w_ih1   = (const float*)d_in[4];
    const float* w_hh1   = (const float*)d_in[5];
    const float* b_ih1   = (const float*)d_in[6];
    const float* b_hh1   = (const float*)d_in[7];
    const float* w_ih2   = (const float*)d_in[8];
    const float* w_hh2   = (const float*)d_in[9];
    const float* b_ih2   = (const float*)d_in[10];
    const float* b_hh2   = (const float*)d_in[11];
    const float* wq      = (const float*)d_in[12];
    const float* bq      = (const float*)d_in[13];
    const float* wp      = (const float*)d_in[14];
    const float* bp      = (const float*)d_in[15];
    float* out = (float*)d_out;

    static int s_attr_done = 0;
    if (!s_attr_done) {
        cudaFuncSetAttribute(k_lstm1, cudaFuncAttributeMaxDynamicSharedMemorySize, L1_SMEM);
        cudaFuncSetAttribute(k_lstm2, cudaFuncAttributeMaxDynamicSharedMemorySize, L2_SMEM);
        cudaFuncSetAttribute(k_pred,  cudaFuncAttributeMaxDynamicSharedMemorySize, KP_SMEM);
        s_attr_done = 1;
    }

    k_prep_small<<<640, 256>>>(w_ih1, w_hh1, b_ih1, b_hh1,
                               w_ih2, w_hh2, b_ih2, b_hh2, wq);
    k_prep_wp<<<dim3(316, 4), 256>>>(wp);
    k_init<<<128, 256>>>();
    for (int s = 0; s < ML; s++) {
        int p = s & 1;
        k_lstm1<<<dim3(8, 16), 512, L1_SMEM>>>(emb, p);
        k_lstm2<<<dim3(4, 32), 256, L2_SMEM>>>(p);
        k_attn<<<256, 256>>>(enc_key, enc_val, mask, bq);
        k_pred<<<dim3(79, 8), 512, KP_SMEM>>>(bp, out, s);
    }
}